// round 1
// baseline (speedup 1.0000x reference)
#include <cuda_runtime.h>
#include <math.h>

// ---------------- problem constants ----------------
#define BATCH   32
#define LSEQ    16
#define BL      512          // BATCH*LSEQ
#define HW      112
#define P49     49           // 7x7 patches
#define M1      25088        // BL * 49
#define C1      576          // patchify out channels
#define K1      768          // 3*16*16
#define DCNN    64
#define K2      5184         // 576*9
#define DRNN    256
#define G3      768          // 3*DRNN
#define DADAPT  16
#define HORIZON 10

// ---------------- scratch (device globals; no cudaMalloc allowed) --------
__device__ float g_f1[M1 * C1];        // conv1 out, channels-last (n,p,576)  ~57.8MB
__device__ float g_y[M1 * DCNN];       // conv2 out (n,p,64)
__device__ float g_w2t[DCNN * K2];     // cnn1_w transposed to [oc][tap*576+ic]
__device__ float g_pool[BL * DCNN];
__device__ float g_s[BL * DRNN];
__device__ float g_gi[BL * G3];        // encoder input gates, row = t*32+b
__device__ float g_wiht[DRNN * G3];    // w_ih^T : [k][g]
__device__ float g_whht[DRNN * G3];    // w_hh^T : [k][g]
__device__ float g_fit[DRNN * DRNN];   // fi_w^T : [k][d]
__device__ float g_h[BATCH * DRNN];
__device__ float g_xi[BATCH * DRNN];

// ---------------- prep: transposes + zero h ----------------
__global__ void prep_kernel(const float* __restrict__ w_ih,
                            const float* __restrict__ w_hh,
                            const float* __restrict__ fi_w,
                            const float* __restrict__ cnn1_w)
{
    int i = blockIdx.x * blockDim.x + threadIdx.x;
    if (i < DRNN * G3) {                 // 196608
        int g = i / DRNN, k = i % DRNN;
        g_wiht[k * G3 + g] = w_ih[i];
        g_whht[k * G3 + g] = w_hh[i];
    }
    if (i < DRNN * DRNN) {               // 65536
        int d = i / DRNN, k = i % DRNN;
        g_fit[k * DRNN + d] = fi_w[i];
    }
    if (i < DCNN * K2) {                 // 331776
        int oc = i / K2, r = i % K2;
        int tap = r / C1, ic = r % C1;
        g_w2t[i] = cnn1_w[oc * K2 + ic * 9 + tap];
    }
    if (i < BATCH * DRNN) g_h[i] = 0.f;
}

__global__ void copy_xi_kernel()
{
    int i = blockIdx.x * blockDim.x + threadIdx.x;
    if (i < BATCH * DRNN) g_xi[i] = g_h[i];
}

// ---------------- GEMM1: patchify conv as GEMM ----------------
// C[m,o] = sum_k A[m,k]*W1[o,k] + b1[o];  m=(n,p), k=(c,dy,dx)
#define BM 128
#define BN 64
#define KT 16

__global__ __launch_bounds__(256) void gemm1_kernel(
    const float* __restrict__ frames,   // (512,3,112,112)
    const float* __restrict__ w1,       // (576,768)
    const float* __restrict__ b1)       // (576)
{
    __shared__ float As[KT][BM + 4];
    __shared__ float Bs[KT][BN + 4];

    int tid = threadIdx.x;
    int kk = tid & 15;
    int ib = tid >> 4;         // 0..15
    int tx = tid & 15;
    int ty = tid >> 4;
    int rowBase = blockIdx.x * BM;
    int colBase = blockIdx.y * BN;

    const float* abase[8];
#pragma unroll
    for (int e = 0; e < 8; e++) {
        int m  = rowBase + ib + e * 16;
        int n  = m / 49;
        int p  = m - n * 49;
        int py = p / 7, px = p - py * 7;
        abase[e] = frames + n * 37632 + py * 1792 + px * 16;
    }

    float acc[8][4];
#pragma unroll
    for (int i = 0; i < 8; i++)
#pragma unroll
        for (int j = 0; j < 4; j++) acc[i][j] = 0.f;

    for (int k0 = 0; k0 < K1; k0 += KT) {
        int k   = k0 + kk;
        int c   = k >> 8;
        int rem = k & 255;
        int aoff = c * 12544 + (rem >> 4) * 112 + (rem & 15);
#pragma unroll
        for (int e = 0; e < 8; e++)
            As[kk][ib + e * 16] = abase[e][aoff];
#pragma unroll
        for (int e = 0; e < 4; e++) {
            int j = ib + e * 16;
            Bs[kk][j] = w1[(colBase + j) * K1 + k];
        }
        __syncthreads();
#pragma unroll
        for (int q = 0; q < KT; q++) {
            float4 a0 = *(const float4*)&As[q][ty * 8];
            float4 a1 = *(const float4*)&As[q][ty * 8 + 4];
            float4 b0 = *(const float4*)&Bs[q][tx * 4];
            float av[8] = {a0.x, a0.y, a0.z, a0.w, a1.x, a1.y, a1.z, a1.w};
            float bv[4] = {b0.x, b0.y, b0.z, b0.w};
#pragma unroll
            for (int i = 0; i < 8; i++)
#pragma unroll
                for (int j = 0; j < 4; j++) acc[i][j] += av[i] * bv[j];
        }
        __syncthreads();
    }

#pragma unroll
    for (int i = 0; i < 8; i++) {
        int m = rowBase + ty * 8 + i;
        float* o = g_f1 + (size_t)m * C1 + colBase + tx * 4;
#pragma unroll
        for (int j = 0; j < 4; j++)
            o[j] = acc[i][j] + b1[colBase + tx * 4 + j];
    }
}

// ---------------- GEMM2: conv3x3 576->64 (SAME) as GEMM ----------------
__global__ __launch_bounds__(256) void gemm2_kernel(const float* __restrict__ b2)
{
    __shared__ float As[KT][BM + 4];
    __shared__ float Bs[KT][BN + 4];

    int tid = threadIdx.x;
    int kk = tid & 15;
    int ib = tid >> 4;
    int tx = tid & 15;
    int ty = tid >> 4;
    int rowBase = blockIdx.x * BM;

    int nrow[8], pyv[8], pxv[8];
#pragma unroll
    for (int e = 0; e < 8; e++) {
        int m = rowBase + ib + e * 16;
        nrow[e] = m / 49;
        int p = m - nrow[e] * 49;
        pyv[e] = p / 7;
        pxv[e] = p - pyv[e] * 7;
    }

    float acc[8][4];
#pragma unroll
    for (int i = 0; i < 8; i++)
#pragma unroll
        for (int j = 0; j < 4; j++) acc[i][j] = 0.f;

    for (int k0 = 0; k0 < K2; k0 += KT) {
        int tap = k0 / C1;                 // constant within a 16-chunk (576%16==0)
        int ic  = k0 - tap * C1 + kk;
        int dy  = tap / 3 - 1, dx = tap - (tap / 3) * 3 - 1;
#pragma unroll
        for (int e = 0; e < 8; e++) {
            int yy = pyv[e] + dy, xx = pxv[e] + dx;
            float v = 0.f;
            if ((unsigned)yy < 7u && (unsigned)xx < 7u)
                v = g_f1[((size_t)nrow[e] * 49 + yy * 7 + xx) * C1 + ic];
            As[kk][ib + e * 16] = v;
        }
#pragma unroll
        for (int e = 0; e < 4; e++) {
            int j = ib + e * 16;
            Bs[kk][j] = g_w2t[j * K2 + k0 + kk];
        }
        __syncthreads();
#pragma unroll
        for (int q = 0; q < KT; q++) {
            float4 a0 = *(const float4*)&As[q][ty * 8];
            float4 a1 = *(const float4*)&As[q][ty * 8 + 4];
            float4 b0 = *(const float4*)&Bs[q][tx * 4];
            float av[8] = {a0.x, a0.y, a0.z, a0.w, a1.x, a1.y, a1.z, a1.w};
            float bv[4] = {b0.x, b0.y, b0.z, b0.w};
#pragma unroll
            for (int i = 0; i < 8; i++)
#pragma unroll
                for (int j = 0; j < 4; j++) acc[i][j] += av[i] * bv[j];
        }
        __syncthreads();
    }

#pragma unroll
    for (int i = 0; i < 8; i++) {
        int m = rowBase + ty * 8 + i;
        float* o = g_y + (size_t)m * DCNN + tx * 4;
#pragma unroll
        for (int j = 0; j < 4; j++)
            o[j] = acc[i][j] + b2[tx * 4 + j];
    }
}

// ---------------- relu + BN + mean-pool ----------------
__global__ void pool_kernel(const float* __restrict__ bn_g,
                            const float* __restrict__ bn_b,
                            const float* __restrict__ bn_m,
                            const float* __restrict__ bn_v)
{
    int n  = blockIdx.x;          // 0..511
    int oc = threadIdx.x;         // 0..63
    float s = 0.f;
    const float* base = g_y + (size_t)n * 49 * DCNN + oc;
#pragma unroll
    for (int p = 0; p < 49; p++) {
        float v = base[p * DCNN];
        s += fmaxf(v, 0.f);
    }
    float inv = bn_g[oc] * rsqrtf(bn_v[oc] + 1e-5f);
    g_pool[n * DCNN + oc] = (s * (1.f / 49.f) - bn_m[oc]) * inv + bn_b[oc];
}

// ---------------- state adapters + concat + an ----------------
__global__ void adapter_kernel(const float* __restrict__ x,
                               const float* __restrict__ a0_w, const float* __restrict__ a0_b,
                               const float* __restrict__ ai_w, const float* __restrict__ ai_b,
                               const float* __restrict__ an_w, const float* __restrict__ an_b)
{
    int r = blockIdx.x;           // b*16 + t
    int tid = threadIdx.x;
    __shared__ float s0[16];
    __shared__ float cat[80];

    const float* xr = x + r * 12;
    if (tid < 16) {
        float a = a0_b[tid];
#pragma unroll
        for (int j = 0; j < 12; j++) a += xr[j] * a0_w[tid * 12 + j];
        s0[tid] = fmaxf(a, 0.f);
    }
    __syncthreads();
    if (tid < 16) {
        float a = ai_b[tid];
#pragma unroll
        for (int j = 0; j < 16; j++) a += s0[j] * ai_w[tid * 16 + j];
        cat[tid] = s0[tid] + fmaxf(a, 0.f);
    }
    if (tid >= 32 && tid < 96) cat[16 + tid - 32] = g_pool[r * DCNN + tid - 32];
    __syncthreads();

    float a = an_b[tid];
#pragma unroll
    for (int j = 0; j < 80; j++) a += cat[j] * an_w[tid * 80 + j];
    g_s[r * DRNN + tid] = fmaxf(a, 0.f);
}

// ---------------- precompute encoder input gates ----------------
__global__ void gi_kernel(const float* __restrict__ b_ih)
{
    int q = blockIdx.x;           // t*32 + b
    int t = q >> 5, b = q & 31;
    int r = b * 16 + t;
    int d = threadIdx.x;
    __shared__ float sv[DRNN];
    sv[d] = g_s[r * DRNN + d];
    __syncthreads();
    float a0 = b_ih[d], a1 = b_ih[256 + d], a2 = b_ih[512 + d];
    for (int k = 0; k < DRNN; k++) {
        float h = sv[k];
        const float* w = g_wiht + k * G3 + d;
        a0 += h * w[0];
        a1 += h * w[256];
        a2 += h * w[512];
    }
    float* o = g_gi + (size_t)q * G3;
    o[d] = a0; o[256 + d] = a1; o[512 + d] = a2;
}

__device__ __forceinline__ float sigmoidf_(float v) { return 1.f / (1.f + expf(-v)); }

// ---------------- one encoder GRU step ----------------
__global__ void gru_enc_kernel(const float* __restrict__ b_hh, int t)
{
    int b = blockIdx.x;
    int d = threadIdx.x;
    __shared__ float hs[DRNN];
    hs[d] = g_h[b * DRNN + d];
    __syncthreads();
    float a0 = b_hh[d], a1 = b_hh[256 + d], a2 = b_hh[512 + d];
    for (int k = 0; k < DRNN; k++) {
        float h = hs[k];
        const float* w = g_whht + k * G3 + d;
        a0 += h * w[0];
        a1 += h * w[256];
        a2 += h * w[512];
    }
    const float* gi = g_gi + (size_t)(t * 32 + b) * G3;
    float rr = sigmoidf_(gi[d] + a0);
    float zz = sigmoidf_(gi[256 + d] + a1);
    float nn = tanhf(gi[512 + d] + rr * a2);
    g_h[b * DRNN + d] = (1.f - zz) * nn + zz * hs[d];
}

// ---------------- one decoder GRU step (gi on the fly) ----------------
__global__ void gru_dec_kernel(const float* __restrict__ b_ih,
                               const float* __restrict__ b_hh)
{
    int b = blockIdx.x;
    int d = threadIdx.x;
    __shared__ float hs[DRNN];
    __shared__ float xs[DRNN];
    hs[d] = g_h[b * DRNN + d];
    xs[d] = g_xi[b * DRNN + d];
    __syncthreads();
    float a0 = b_hh[d], a1 = b_hh[256 + d], a2 = b_hh[512 + d];
    float c0 = b_ih[d], c1 = b_ih[256 + d], c2 = b_ih[512 + d];
    for (int k = 0; k < DRNN; k++) {
        float h = hs[k];
        float xv = xs[k];
        const float* wh = g_whht + k * G3 + d;
        const float* wi = g_wiht + k * G3 + d;
        a0 += h * wh[0];  a1 += h * wh[256];  a2 += h * wh[512];
        c0 += xv * wi[0]; c1 += xv * wi[256]; c2 += xv * wi[512];
    }
    float rr = sigmoidf_(c0 + a0);
    float zz = sigmoidf_(c1 + a1);
    float nn = tanhf(c2 + rr * a2);
    g_h[b * DRNN + d] = (1.f - zz) * nn + zz * hs[d];
}

// ---------------- decode epilogue: residual + pred head ----------------
__global__ void dec_out_kernel(const float* __restrict__ fi_b,
                               const float* __restrict__ fn_w,
                               const float* __restrict__ fn_b,
                               float* __restrict__ out, int t)
{
    int b = blockIdx.x;
    int d = threadIdx.x;
    __shared__ float hn[DRNN];
    __shared__ float xr[DRNN];
    hn[d] = g_h[b * DRNN + d];
    __syncthreads();
    float a = fi_b[d];
    for (int k = 0; k < DRNN; k++) a += hn[k] * g_fit[k * DRNN + d];
    float v = hn[d] + fmaxf(a, 0.f);
    xr[d] = v;
    g_xi[b * DRNN + d] = v;
    __syncthreads();
    if (d < 2) {
        float s = fn_b[d];
        for (int k = 0; k < DRNN; k++) s += xr[k] * fn_w[d * DRNN + k];
        out[(t * 32 + b) * 2 + d] = tanhf(s);
    }
}

// ---------------- launch ----------------
extern "C" void kernel_launch(void* const* d_in, const int* in_sizes, int n_in,
                              void* d_out, int out_size)
{
    const float* x      = (const float*)d_in[0];
    const float* frames = (const float*)d_in[1];
    const float* cnn_w  = (const float*)d_in[2];
    const float* cnn_b  = (const float*)d_in[3];
    const float* cnn1_w = (const float*)d_in[4];
    const float* cnn1_b = (const float*)d_in[5];
    const float* bn_g   = (const float*)d_in[6];
    const float* bn_b   = (const float*)d_in[7];
    const float* bn_m   = (const float*)d_in[8];
    const float* bn_v   = (const float*)d_in[9];
    const float* a0_w   = (const float*)d_in[10];
    const float* a0_b   = (const float*)d_in[11];
    const float* ai_w   = (const float*)d_in[12];
    const float* ai_b   = (const float*)d_in[13];
    const float* an_w   = (const float*)d_in[14];
    const float* an_b   = (const float*)d_in[15];
    const float* w_ih   = (const float*)d_in[16];
    const float* w_hh   = (const float*)d_in[17];
    const float* b_ih   = (const float*)d_in[18];
    const float* b_hh   = (const float*)d_in[19];
    const float* fi_w   = (const float*)d_in[20];
    const float* fi_b   = (const float*)d_in[21];
    const float* fn_w   = (const float*)d_in[22];
    const float* fn_b   = (const float*)d_in[23];
    float* out = (float*)d_out;

    // transposes + zero h
    prep_kernel<<<(DCNN * K2 + 255) / 256, 256>>>(w_ih, w_hh, fi_w, cnn1_w);

    // conv1 GEMM: 25088 x 576, K=768
    dim3 g1(M1 / BM, C1 / BN);
    gemm1_kernel<<<g1, 256>>>(frames, cnn_w, cnn_b);

    // conv2 GEMM: 25088 x 64, K=5184
    gemm2_kernel<<<M1 / BM, 256>>>(cnn1_b);

    // relu+bn+pool
    pool_kernel<<<BL, DCNN>>>(bn_g, bn_b, bn_m, bn_v);

    // adapters
    adapter_kernel<<<BL, DRNN>>>(x, a0_w, a0_b, ai_w, ai_b, an_w, an_b);

    // encoder input gates
    gi_kernel<<<BL, DRNN>>>(b_ih);

    // encoder GRU
    for (int t = 0; t < LSEQ; t++)
        gru_enc_kernel<<<BATCH, DRNN>>>(b_hh, t);

    // x_in = h
    copy_xi_kernel<<<(BATCH * DRNN + 255) / 256, 256>>>();

    // autoregressive decode
    for (int t = 0; t < HORIZON; t++) {
        gru_dec_kernel<<<BATCH, DRNN>>>(b_ih, b_hh);
        dec_out_kernel<<<BATCH, DRNN>>>(fi_b, fn_w, fn_b, out, t);
    }
}